// round 2
// baseline (speedup 1.0000x reference)
#include <cuda_runtime.h>
#include <math.h>

#define NMAX 100000
#define EMAX 1700000
#define DMAX 64

// ---------------- scratch (device globals; no allocation allowed) ----------
__device__ int   g_is64;
__device__ int   g_cnt[NMAX];
__device__ int   g_off[NMAX + 1];
__device__ int   g_esrc[EMAX];
__device__ float g_e[EMAX];
__device__ __align__(16) float g_h[(size_t)NMAX * DMAX];
__device__ __align__(16) float g_bufA[(size_t)NMAX * DMAX];
__device__ __align__(16) float g_bufB[(size_t)NMAX * DMAX];
__device__ float g_as[NMAX];
__device__ float g_ad[NMAX];

// ---------------- dtype detection ----------------
// int64 little-endian indices < 2^31 have all odd 32-bit words == 0.
// int32 random node ids make that essentially impossible over 64 samples.
__global__ void detect_kernel(const unsigned int* __restrict__ w) {
    if (threadIdx.x != 0 || blockIdx.x != 0) return;
    int ok64 = 1;
#pragma unroll
    for (int i = 1; i < 128; i += 2) ok64 &= (w[i] == 0u);
    g_is64 = ok64;
}

__device__ __forceinline__ int load_idx(const void* eiv, long long pos) {
    int v;
    if (g_is64) v = (int)((const long long*)eiv)[pos];
    else        v = ((const int*)eiv)[pos];
    return v;
}

__device__ __forceinline__ int clampN(int v, int N) {
    return (v < 0) ? 0 : (v >= N ? N - 1 : v);
}

// ---------------- CSR build ----------------
__global__ void zero_cnt_kernel(int N) {
    int i = blockIdx.x * blockDim.x + threadIdx.x;
    if (i < N) g_cnt[i] = 0;
}

__global__ void hist_kernel(const void* __restrict__ eiv, int E, int Etot, int N) {
    int i = blockIdx.x * blockDim.x + threadIdx.x;
    if (i >= Etot) return;
    int d = (i < E) ? clampN(load_idx(eiv, (long long)E + i), N) : (i - E);
    atomicAdd(&g_cnt[d], 1);
}

__global__ void scan_kernel(int N) {
    __shared__ int part[1024];
    int tid = threadIdx.x;
    int chunk = (N + 1023) / 1024;
    int b = tid * chunk;
    int e = min(b + chunk, N);
    int s = 0;
    for (int i = b; i < e; i++) s += g_cnt[i];
    part[tid] = s;
    __syncthreads();
    for (int o = 1; o < 1024; o <<= 1) {
        int v = (tid >= o) ? part[tid - o] : 0;
        __syncthreads();
        part[tid] += v;
        __syncthreads();
    }
    int pre = (tid == 0) ? 0 : part[tid - 1];
    for (int i = b; i < e; i++) {
        int c = g_cnt[i];
        g_off[i] = pre;
        g_cnt[i] = pre;        // becomes the scatter cursor
        pre += c;
    }
    if (tid == 1023) g_off[N] = part[1023];
}

__global__ void scatter_kernel(const void* __restrict__ eiv, int E, int Etot, int N) {
    int i = blockIdx.x * blockDim.x + threadIdx.x;
    if (i >= Etot) return;
    int s, d;
    if (i < E) {
        s = clampN(load_idx(eiv, i), N);
        d = clampN(load_idx(eiv, (long long)E + i), N);
    } else {
        s = d = i - E;
    }
    int p = atomicAdd(&g_cnt[d], 1);
    if (p >= 0 && p < EMAX) g_esrc[p] = s;
}

// ---------------- GEMM: h = X @ W  (X: [N,F], W: [F,D], D<=64, F%16==0) ----
__global__ __launch_bounds__(256) void gemm_kernel(
    const float* __restrict__ Xext, int sel_in,
    const float* __restrict__ W, int N, int F, int D, int relu_in)
{
    const float* X = (sel_in == 0) ? Xext
                   : (sel_in == 1 ? (const float*)g_bufA : (const float*)g_bufB);
    __shared__ __align__(16) float xs[16][66];   // [k][node], padded
    __shared__ __align__(16) float ws[16][64];   // [k][col]
    int tid  = threadIdx.x;
    int row0 = blockIdx.x * 64;
    int tr = tid >> 4, tc = tid & 15;
    float acc[4][4] = {};
    int lnode = tid >> 2, lq = tid & 3;
    int wcol = tid & 63, wk0 = (tid >> 6) << 2;

    for (int k0 = 0; k0 < F; k0 += 16) {
        float4 xv = make_float4(0.f, 0.f, 0.f, 0.f);
        int gn = row0 + lnode;
        if (gn < N)
            xv = reinterpret_cast<const float4*>(X + (size_t)gn * F + k0)[lq];
        if (relu_in) {
            xv.x = fmaxf(xv.x, 0.f); xv.y = fmaxf(xv.y, 0.f);
            xv.z = fmaxf(xv.z, 0.f); xv.w = fmaxf(xv.w, 0.f);
        }
        xs[lq * 4 + 0][lnode] = xv.x;
        xs[lq * 4 + 1][lnode] = xv.y;
        xs[lq * 4 + 2][lnode] = xv.z;
        xs[lq * 4 + 3][lnode] = xv.w;
#pragma unroll
        for (int j = 0; j < 4; j++) {
            int k = wk0 + j;
            ws[k][wcol] = (wcol < D) ? W[(size_t)(k0 + k) * D + wcol] : 0.f;
        }
        __syncthreads();
#pragma unroll
        for (int k = 0; k < 16; k++) {
            float a0 = xs[k][tr * 4 + 0], a1 = xs[k][tr * 4 + 1];
            float a2 = xs[k][tr * 4 + 2], a3 = xs[k][tr * 4 + 3];
            float b0 = ws[k][tc * 4 + 0], b1 = ws[k][tc * 4 + 1];
            float b2 = ws[k][tc * 4 + 2], b3 = ws[k][tc * 4 + 3];
            acc[0][0] += a0 * b0; acc[0][1] += a0 * b1; acc[0][2] += a0 * b2; acc[0][3] += a0 * b3;
            acc[1][0] += a1 * b0; acc[1][1] += a1 * b1; acc[1][2] += a1 * b2; acc[1][3] += a1 * b3;
            acc[2][0] += a2 * b0; acc[2][1] += a2 * b1; acc[2][2] += a2 * b2; acc[2][3] += a2 * b3;
            acc[3][0] += a3 * b0; acc[3][1] += a3 * b1; acc[3][2] += a3 * b2; acc[3][3] += a3 * b3;
        }
        __syncthreads();
    }
#pragma unroll
    for (int i = 0; i < 4; i++) {
        int n = row0 + tr * 4 + i;
        if (n >= N) continue;
#pragma unroll
        for (int j = 0; j < 4; j++) {
            int c = tc * 4 + j;
            if (c < D) g_h[(size_t)n * D + c] = acc[i][j];
        }
    }
}

// ---------------- per-node attention dot products ----------------
__global__ void attn_dots_kernel(const float* __restrict__ a_s,
                                 const float* __restrict__ a_d, int N, int D)
{
    int warp = (blockIdx.x * blockDim.x + threadIdx.x) >> 5;
    int lane = threadIdx.x & 31;
    int nw = (gridDim.x * blockDim.x) >> 5;
    for (int n = warp; n < N; n += nw) {
        float s = 0.f, d = 0.f;
        for (int c = lane; c < D; c += 32) {
            float hv = g_h[(size_t)n * D + c];
            s += hv * a_s[c];
            d += hv * a_d[c];
        }
#pragma unroll
        for (int o = 16; o; o >>= 1) {
            s += __shfl_xor_sync(0xffffffffu, s, o);
            d += __shfl_xor_sync(0xffffffffu, d, o);
        }
        if (lane == 0) { g_as[n] = s; g_ad[n] = d; }
    }
}

// ---------------- fused segment softmax + aggregation (warp per dst) -------
__global__ void agg_kernel(float* OUText, int sel_out, int N, int D)
{
    float* OUT = (sel_out == 0) ? OUText : (sel_out == 1 ? g_bufA : g_bufB);
    int warp = (blockIdx.x * blockDim.x + threadIdx.x) >> 5;
    int lane = threadIdx.x & 31;
    int nw = (gridDim.x * blockDim.x) >> 5;
    const float2* H2 = reinterpret_cast<const float2*>(g_h);
    int rowst = D >> 1;

    for (int n = warp; n < N; n += nw) {
        int beg = g_off[n], end = g_off[n + 1];
        float adn = g_ad[n];

        // pass 1: segment max of leaky_relu(as[src]+ad[n])
        float m = -INFINITY;
        for (int p = beg + lane; p < end; p += 32) {
            float v = g_as[g_esrc[p]] + adn;
            v = (v > 0.f) ? v : 0.2f * v;
            m = fmaxf(m, v);
        }
#pragma unroll
        for (int o = 16; o; o >>= 1) m = fmaxf(m, __shfl_xor_sync(0xffffffffu, m, o));

        // pass 2: exp + segment sum (store ex per edge)
        float sum = 0.f;
        for (int p = beg + lane; p < end; p += 32) {
            float v = g_as[g_esrc[p]] + adn;
            v = (v > 0.f) ? v : 0.2f * v;
            float ex = __expf(v - m);
            g_e[p] = ex;
            sum += ex;
        }
#pragma unroll
        for (int o = 16; o; o >>= 1) sum += __shfl_xor_sync(0xffffffffu, sum, o);
        float inv = 1.f / (sum + 1e-16f);

        // pass 3: out[n,:] = sum_e alpha_e * h[src_e,:]   (lane owns 2 cols)
        int c0 = lane * 2;
        bool act = (c0 < D);
        float2 acc = make_float2(0.f, 0.f);
        for (int p = beg; p < end; p++) {
            float alpha = g_e[p] * inv;     // uniform: broadcast load
            int s = g_esrc[p];              // uniform: broadcast load
            if (act) {
                float2 hv = H2[(size_t)s * rowst + lane];
                acc.x += alpha * hv.x;
                acc.y += alpha * hv.y;
            }
        }
        if (act) {
            OUT[(size_t)n * D + c0]     = acc.x;
            OUT[(size_t)n * D + c0 + 1] = acc.y;
        }
    }
}

// ---------------- launch ----------------
extern "C" void kernel_launch(void* const* d_in, const int* in_sizes, int n_in,
                              void* d_out, int out_size)
{
    const float* x     = (const float*)d_in[0];
    const void*  ei    = d_in[1];
    const float* W0    = (const float*)d_in[2];
    const float* asrc0 = (const float*)d_in[3];
    const float* adst0 = (const float*)d_in[4];
    const float* W1    = (const float*)d_in[5];
    const float* asrc1 = (const float*)d_in[6];
    const float* adst1 = (const float*)d_in[7];
    const float* W2    = (const float*)d_in[8];
    const float* asrc2 = (const float*)d_in[9];
    const float* adst2 = (const float*)d_in[10];

    int H    = in_sizes[3];            // 64
    int C    = in_sizes[9];            // 40
    int Fin  = in_sizes[2] / H;        // 256
    int N    = in_sizes[0] / Fin;      // 100000
    int E    = in_sizes[1] / 2;        // 1600000
    int Etot = E + N;

    // dtype detection + CSR build (once per call, reused by all 3 layers)
    detect_kernel<<<1, 32>>>((const unsigned int*)ei);
    zero_cnt_kernel<<<(N + 255) / 256, 256>>>(N);
    hist_kernel<<<(Etot + 255) / 256, 256>>>(ei, E, Etot, N);
    scan_kernel<<<1, 1024>>>(N);
    scatter_kernel<<<(Etot + 255) / 256, 256>>>(ei, E, Etot, N);

    int gemm_blocks = (N + 63) / 64;
    int wg_blocks   = (N + 7) / 8;   // one warp per node, 8 warps/block

    // layer 0: x -> bufA
    gemm_kernel<<<gemm_blocks, 256>>>(x, 0, W0, N, Fin, H, 0);
    attn_dots_kernel<<<wg_blocks, 256>>>(asrc0, adst0, N, H);
    agg_kernel<<<wg_blocks, 256>>>(nullptr, 1, N, H);

    // layer 1: relu(bufA) -> bufB
    gemm_kernel<<<gemm_blocks, 256>>>(nullptr, 1, W1, N, H, H, 1);
    attn_dots_kernel<<<wg_blocks, 256>>>(asrc1, adst1, N, H);
    agg_kernel<<<wg_blocks, 256>>>(nullptr, 2, N, H);

    // layer 2: relu(bufB) -> d_out
    gemm_kernel<<<gemm_blocks, 256>>>(nullptr, 2, W2, N, H, C, 1);
    attn_dots_kernel<<<wg_blocks, 256>>>(asrc2, adst2, N, C);
    agg_kernel<<<wg_blocks, 256>>>((float*)d_out, 0, N, C);
}

// round 3
// speedup vs baseline: 1.4998x; 1.4998x over previous
#include <cuda_runtime.h>
#include <math.h>

#define NMAX 100000
#define EMAX 1700000
#define DMAX 64
#define SCAN_CHUNK 512   // elements per block in the scan

// ---------------- scratch (device globals; no allocation allowed) ----------
__device__ int   g_is64;
__device__ int   g_cnt[NMAX];
__device__ int   g_off[NMAX + 1];
__device__ int   g_part[1024];
__device__ int   g_esrc[EMAX];
__device__ float g_e[EMAX];
__device__ __align__(16) float g_h[(size_t)NMAX * DMAX];
__device__ __align__(16) float g_bufA[(size_t)NMAX * DMAX];
__device__ __align__(16) float g_bufB[(size_t)NMAX * DMAX];
__device__ float g_as[NMAX];
__device__ float g_ad[NMAX];

// ---------------- dtype detection ----------------
__global__ void detect_kernel(const unsigned int* __restrict__ w) {
    if (threadIdx.x != 0 || blockIdx.x != 0) return;
    int ok64 = 1;
#pragma unroll
    for (int i = 1; i < 128; i += 2) ok64 &= (w[i] == 0u);
    g_is64 = ok64;
}

__device__ __forceinline__ int load_idx(const void* eiv, long long pos) {
    if (g_is64) return (int)((const long long*)eiv)[pos];
    return ((const int*)eiv)[pos];
}

__device__ __forceinline__ int clampN(int v, int N) {
    return (v < 0) ? 0 : (v >= N ? N - 1 : v);
}

// ---------------- CSR build ----------------
__global__ void zero_cnt_kernel(int N) {
    int i = blockIdx.x * blockDim.x + threadIdx.x;
    if (i < N) g_cnt[i] = 0;
}

__global__ void hist_kernel(const void* __restrict__ eiv, int E, int Etot, int N) {
    int i = blockIdx.x * blockDim.x + threadIdx.x;
    if (i >= Etot) return;
    int d = (i < E) ? clampN(load_idx(eiv, (long long)E + i), N) : (i - E);
    atomicAdd(&g_cnt[d], 1);
}

// ---- 3-phase scan ----
// phase 1: per-block sums of SCAN_CHUNK counts
__global__ void scan_reduce_kernel(int N) {
    __shared__ int sh[256];
    int b = blockIdx.x, t = threadIdx.x;
    int i0 = b * SCAN_CHUNK + t * 2;
    int s = 0;
    if (i0     < N) s += g_cnt[i0];
    if (i0 + 1 < N) s += g_cnt[i0 + 1];
    sh[t] = s;
    __syncthreads();
#pragma unroll
    for (int o = 128; o; o >>= 1) {
        if (t < o) sh[t] += sh[t + o];
        __syncthreads();
    }
    if (t == 0) g_part[b] = sh[0];
}

// phase 2: exclusive scan of B block partials (B <= 1024), writes total to g_off[N]
__global__ void scan_partials_kernel(int B, int N) {
    __shared__ int sh[1024];
    int t = threadIdx.x;
    int v = (t < B) ? g_part[t] : 0;
    sh[t] = v;
    __syncthreads();
#pragma unroll
    for (int o = 1; o < 1024; o <<= 1) {
        int u = (t >= o) ? sh[t - o] : 0;
        __syncthreads();
        sh[t] += u;
        __syncthreads();
    }
    if (t < B) g_part[t] = sh[t] - v;         // exclusive
    if (t == 1023) g_off[N] = sh[1023];       // grand total
}

// phase 3: block-local exclusive scan + base offset; writes g_off and cursors
__global__ void scan_final_kernel(int N) {
    __shared__ int sh[256];
    int b = blockIdx.x, t = threadIdx.x;
    int i0 = b * SCAN_CHUNK + t * 2;
    int c0 = (i0     < N) ? g_cnt[i0]     : 0;
    int c1 = (i0 + 1 < N) ? g_cnt[i0 + 1] : 0;
    int s = c0 + c1;
    sh[t] = s;
    __syncthreads();
#pragma unroll
    for (int o = 1; o < 256; o <<= 1) {
        int u = (t >= o) ? sh[t - o] : 0;
        __syncthreads();
        sh[t] += u;
        __syncthreads();
    }
    int base = g_part[b] + sh[t] - s;  // exclusive prefix for this thread
    if (i0 < N)     { g_off[i0]     = base;      g_cnt[i0]     = base; }
    if (i0 + 1 < N) { g_off[i0 + 1] = base + c0; g_cnt[i0 + 1] = base + c0; }
}

__global__ void scatter_kernel(const void* __restrict__ eiv, int E, int Etot, int N) {
    int i = blockIdx.x * blockDim.x + threadIdx.x;
    if (i >= Etot) return;
    int s, d;
    if (i < E) {
        s = clampN(load_idx(eiv, i), N);
        d = clampN(load_idx(eiv, (long long)E + i), N);
    } else {
        s = d = i - E;
    }
    int p = atomicAdd(&g_cnt[d], 1);
    if (p >= 0 && p < EMAX) g_esrc[p] = s;
}

// ---------------- GEMM + fused attention dots ----------------
// h = X @ W  (X: [N,F], W: [F,D], D<=64, F%16==0); also g_as/g_ad = h @ a_s/a_d
__global__ __launch_bounds__(256) void gemm_kernel(
    const float* __restrict__ Xext, int sel_in,
    const float* __restrict__ W,
    const float* __restrict__ a_s, const float* __restrict__ a_d,
    int N, int F, int D, int relu_in)
{
    const float* X = (sel_in == 0) ? Xext
                   : (sel_in == 1 ? (const float*)g_bufA : (const float*)g_bufB);
    __shared__ __align__(16) float xs[16][66];
    __shared__ __align__(16) float ws[16][64];
    __shared__ float as_s[64], ad_s[64];
    int tid  = threadIdx.x;
    int row0 = blockIdx.x * 64;
    int tr = tid >> 4, tc = tid & 15;
    float acc[4][4] = {};
    int lnode = tid >> 2, lq = tid & 3;
    int wcol = tid & 63, wk0 = (tid >> 6) << 2;

    if (tid < 64) {
        as_s[tid] = (tid < D) ? a_s[tid] : 0.f;
        ad_s[tid] = (tid < D) ? a_d[tid] : 0.f;
    }

    for (int k0 = 0; k0 < F; k0 += 16) {
        float4 xv = make_float4(0.f, 0.f, 0.f, 0.f);
        int gn = row0 + lnode;
        if (gn < N)
            xv = reinterpret_cast<const float4*>(X + (size_t)gn * F + k0)[lq];
        if (relu_in) {
            xv.x = fmaxf(xv.x, 0.f); xv.y = fmaxf(xv.y, 0.f);
            xv.z = fmaxf(xv.z, 0.f); xv.w = fmaxf(xv.w, 0.f);
        }
        xs[lq * 4 + 0][lnode] = xv.x;
        xs[lq * 4 + 1][lnode] = xv.y;
        xs[lq * 4 + 2][lnode] = xv.z;
        xs[lq * 4 + 3][lnode] = xv.w;
#pragma unroll
        for (int j = 0; j < 4; j++) {
            int k = wk0 + j;
            ws[k][wcol] = (wcol < D) ? W[(size_t)(k0 + k) * D + wcol] : 0.f;
        }
        __syncthreads();
#pragma unroll
        for (int k = 0; k < 16; k++) {
            float a0 = xs[k][tr * 4 + 0], a1 = xs[k][tr * 4 + 1];
            float a2 = xs[k][tr * 4 + 2], a3 = xs[k][tr * 4 + 3];
            float b0 = ws[k][tc * 4 + 0], b1 = ws[k][tc * 4 + 1];
            float b2 = ws[k][tc * 4 + 2], b3 = ws[k][tc * 4 + 3];
            acc[0][0] += a0 * b0; acc[0][1] += a0 * b1; acc[0][2] += a0 * b2; acc[0][3] += a0 * b3;
            acc[1][0] += a1 * b0; acc[1][1] += a1 * b1; acc[1][2] += a1 * b2; acc[1][3] += a1 * b3;
            acc[2][0] += a2 * b0; acc[2][1] += a2 * b1; acc[2][2] += a2 * b2; acc[2][3] += a2 * b3;
            acc[3][0] += a3 * b0; acc[3][1] += a3 * b1; acc[3][2] += a3 * b2; acc[3][3] += a3 * b3;
        }
        __syncthreads();
    }

    // epilogue: store h + fused attention dot-products
    float sdot[4] = {}, ddot[4] = {};
#pragma unroll
    for (int i = 0; i < 4; i++) {
        int n = row0 + tr * 4 + i;
        bool ok = (n < N);
#pragma unroll
        for (int j = 0; j < 4; j++) {
            int c = tc * 4 + j;
            if (ok && c < D) g_h[(size_t)n * D + c] = acc[i][j];
            float w = (c < D) ? acc[i][j] : 0.f;
            sdot[i] += w * as_s[c];
            ddot[i] += w * ad_s[c];
        }
    }
    // reduce across the 16 tc lanes (xor offsets < 16 stay in the group)
#pragma unroll
    for (int o = 8; o; o >>= 1) {
#pragma unroll
        for (int i = 0; i < 4; i++) {
            sdot[i] += __shfl_xor_sync(0xffffffffu, sdot[i], o);
            ddot[i] += __shfl_xor_sync(0xffffffffu, ddot[i], o);
        }
    }
    if (tc == 0) {
#pragma unroll
        for (int i = 0; i < 4; i++) {
            int n = row0 + tr * 4 + i;
            if (n < N) { g_as[n] = sdot[i]; g_ad[n] = ddot[i]; }
        }
    }
}

// ---------------- fused segment softmax + aggregation (warp per dst) -------
__global__ void agg_kernel(float* OUText, int sel_out, int N, int D)
{
    float* OUT = (sel_out == 0) ? OUText : (sel_out == 1 ? g_bufA : g_bufB);
    int warp = (blockIdx.x * blockDim.x + threadIdx.x) >> 5;
    int lane = threadIdx.x & 31;
    int nw = (gridDim.x * blockDim.x) >> 5;
    const float2* H2 = reinterpret_cast<const float2*>(g_h);
    int rowst = D >> 1;

    for (int n = warp; n < N; n += nw) {
        int beg = g_off[n], end = g_off[n + 1];
        float adn = g_ad[n];

        // pass 1: compute logits, cache them, segment max
        float m = -INFINITY;
        for (int p = beg + lane; p < end; p += 32) {
            float v = g_as[g_esrc[p]] + adn;
            v = (v > 0.f) ? v : 0.2f * v;
            g_e[p] = v;
            m = fmaxf(m, v);
        }
#pragma unroll
        for (int o = 16; o; o >>= 1) m = fmaxf(m, __shfl_xor_sync(0xffffffffu, m, o));

        // pass 2: exp from cached logits + segment sum (store ex back)
        float sum = 0.f;
        for (int p = beg + lane; p < end; p += 32) {
            float ex = __expf(g_e[p] - m);
            g_e[p] = ex;
            sum += ex;
        }
#pragma unroll
        for (int o = 16; o; o >>= 1) sum += __shfl_xor_sync(0xffffffffu, sum, o);
        float inv = 1.f / (sum + 1e-16f);

        // pass 3: out[n,:] = sum_e alpha_e * h[src_e,:]  (lane owns 2 cols)
        int c0 = lane * 2;
        bool act = (c0 < D);
        float2 acc = make_float2(0.f, 0.f);
        int p = beg;
        for (; p + 1 < end; p += 2) {
            float a0 = g_e[p] * inv;
            float a1 = g_e[p + 1] * inv;
            int s0 = g_esrc[p];
            int s1 = g_esrc[p + 1];
            if (act) {
                float2 h0 = H2[(size_t)s0 * rowst + lane];
                float2 h1 = H2[(size_t)s1 * rowst + lane];
                acc.x += a0 * h0.x + a1 * h1.x;
                acc.y += a0 * h0.y + a1 * h1.y;
            }
        }
        if (p < end) {
            float a0 = g_e[p] * inv;
            int s0 = g_esrc[p];
            if (act) {
                float2 h0 = H2[(size_t)s0 * rowst + lane];
                acc.x += a0 * h0.x;
                acc.y += a0 * h0.y;
            }
        }
        if (act) {
            OUT[(size_t)n * D + c0]     = acc.x;
            OUT[(size_t)n * D + c0 + 1] = acc.y;
        }
    }
}

// ---------------- launch ----------------
extern "C" void kernel_launch(void* const* d_in, const int* in_sizes, int n_in,
                              void* d_out, int out_size)
{
    const float* x     = (const float*)d_in[0];
    const void*  ei    = d_in[1];
    const float* W0    = (const float*)d_in[2];
    const float* asrc0 = (const float*)d_in[3];
    const float* adst0 = (const float*)d_in[4];
    const float* W1    = (const float*)d_in[5];
    const float* asrc1 = (const float*)d_in[6];
    const float* adst1 = (const float*)d_in[7];
    const float* W2    = (const float*)d_in[8];
    const float* asrc2 = (const float*)d_in[9];
    const float* adst2 = (const float*)d_in[10];

    int H    = in_sizes[3];            // 64
    int C    = in_sizes[9];            // 40
    int Fin  = in_sizes[2] / H;        // 256
    int N    = in_sizes[0] / Fin;      // 100000
    int E    = in_sizes[1] / 2;        // 1600000
    int Etot = E + N;
    int SB   = (N + SCAN_CHUNK - 1) / SCAN_CHUNK;   // scan blocks (196)

    // dtype detection + CSR build
    detect_kernel<<<1, 32>>>((const unsigned int*)ei);
    zero_cnt_kernel<<<(N + 255) / 256, 256>>>(N);
    hist_kernel<<<(Etot + 255) / 256, 256>>>(ei, E, Etot, N);
    scan_reduce_kernel<<<SB, 256>>>(N);
    scan_partials_kernel<<<1, 1024>>>(SB, N);
    scan_final_kernel<<<SB, 256>>>(N);
    scatter_kernel<<<(Etot + 255) / 256, 256>>>(ei, E, Etot, N);

    int gemm_blocks = (N + 63) / 64;
    int wg_blocks   = (N + 7) / 8;   // one warp per node, 8 warps/block

    // layer 0: x -> bufA
    gemm_kernel<<<gemm_blocks, 256>>>(x, 0, W0, asrc0, adst0, N, Fin, H, 0);
    agg_kernel<<<wg_blocks, 256>>>(nullptr, 1, N, H);

    // layer 1: relu(bufA) -> bufB
    gemm_kernel<<<gemm_blocks, 256>>>(nullptr, 1, W1, asrc1, adst1, N, H, H, 1);
    agg_kernel<<<wg_blocks, 256>>>(nullptr, 2, N, H);

    // layer 2: relu(bufB) -> d_out
    gemm_kernel<<<gemm_blocks, 256>>>(nullptr, 2, W2, asrc2, adst2, N, H, C, 1);
    agg_kernel<<<wg_blocks, 256>>>((float*)d_out, 0, N, C);
}